// round 13
// baseline (speedup 1.0000x reference)
#include <cuda_runtime.h>
#include <cstdint>
#include <math.h>

#define NUM_USERS 8192
#define NUM_ITEMS 32768
#define FEAT      129
#define BM        128
#define BN        64
#define NTHREADS  128              // 4 warps, each 64x32 (dual s32 accumulators)

// ---- scratch (__device__ globals: allocation-free) ----
// per row 256 bytes: [ xh(128 int8) | xl(128 int8) ],  x ~= s*(xh + xl/128)
__device__ __align__(256) signed char g_A8[(size_t)NUM_USERS * 256];
__device__ __align__(256) signed char g_B8[(size_t)NUM_ITEMS * 256];
__device__ float g_sA[NUM_USERS];
__device__ float g_sB[NUM_ITEMS];
__device__ float g_A129[NUM_USERS];   // feature 128, exact fp32 (rank-1 peel)
__device__ float g_B129[NUM_ITEMS];

__device__ __forceinline__ uint32_t smem_u32(const void* p) {
    uint32_t a;
    asm("{ .reg .u64 t; cvta.to.shared.u64 t, %1; cvt.u32.u64 %0, t; }" : "=r"(a) : "l"(p));
    return a;
}
#define SW128(off) ((off) ^ (((off) >> 3) & 0x70))

// ---- prep: warp-per-row int8 two-term quantization + sign fold + rank-1 peel ----
__global__ void prep_kernel(const float* __restrict__ h) {
    int warp = (blockIdx.x * blockDim.x + threadIdx.x) >> 5;
    int L = threadIdx.x & 31;
    if (warp >= NUM_USERS + NUM_ITEMS) return;
    const bool isUser = warp < NUM_USERS;
    const float* row = h + (size_t)warp * FEAT;
    float v[4];
    #pragma unroll
    for (int j = 0; j < 4; j++) {
        v[j] = row[L + 32 * j];
        if (!isUser && (L + 32 * j) == 0) v[j] = -v[j];   // signs[0] = -1 folded into items
    }
    float m = fmaxf(fmaxf(fabsf(v[0]), fabsf(v[1])), fmaxf(fabsf(v[2]), fabsf(v[3])));
    #pragma unroll
    for (int o = 16; o; o >>= 1) m = fmaxf(m, __shfl_xor_sync(0xffffffffu, m, o));
    float s = (m > 0.0f) ? m * (1.0f / 127.0f) : 1.0f;
    float inv = 1.0f / s;
    signed char* dst = isUser ? (g_A8 + (size_t)warp * 256)
                              : (g_B8 + (size_t)(warp - NUM_USERS) * 256);
    #pragma unroll
    for (int j = 0; j < 4; j++) {
        int k = L + 32 * j;
        float ahf = rintf(v[j] * inv);
        ahf = fminf(fmaxf(ahf, -127.0f), 127.0f);
        float r = v[j] - ahf * s;
        float alf = rintf(r * inv * 128.0f);
        alf = fminf(fmaxf(alf, -127.0f), 127.0f);
        dst[k]       = (signed char)(int)ahf;
        dst[128 + k] = (signed char)(int)alf;
    }
    if (L == 0) {
        if (isUser) { g_sA[warp] = s; g_A129[warp] = row[128]; }
        else        { g_sB[warp - NUM_USERS] = s; g_B129[warp - NUM_USERS] = row[128]; }
    }
}

// smem: Ah[16K] | Al[16K] | Bh[8K] | Bl[8K] = 48KB, loaded once (no pipeline)
#define OFF_AH 0
#define OFF_AL 16384
#define OFF_BH 32768
#define OFF_BL 40960

__global__ __launch_bounds__(NTHREADS, 3)
void gemm_i8_kernel(float* __restrict__ out) {
    __shared__ __align__(1024) signed char smem[49152];
    const uint32_t sb = smem_u32(smem);
    const int tid = threadIdx.x;
    const int wid = tid >> 5;
    const int L = tid & 31;
    const int m0 = blockIdx.x * BM;
    const int n0 = blockIdx.y * BN;
    const int mb = (wid & 1) * 64;    // 2 warps in m
    const int nb = (wid >> 1) * 32;   // 2 warps in n

    // ---- one-shot cooperative load of the full K (256B/row) via cp.async ----
    {
        const signed char* srcA = g_A8 + (size_t)m0 * 256;
        const signed char* srcB = g_B8 + (size_t)n0 * 256;
        #pragma unroll
        for (int it = 0; it < 8; it++) {   // Ah: 1024 x 16B
            int idx = tid + it * NTHREADS; int row = idx >> 3, sg = idx & 7;
            uint32_t off = row * 128 + sg * 16;
            asm volatile("cp.async.cg.shared.global [%0], [%1], 16;"
                :: "r"(sb + OFF_AH + SW128(off)), "l"(srcA + row * 256 + sg * 16));
        }
        #pragma unroll
        for (int it = 0; it < 8; it++) {   // Al
            int idx = tid + it * NTHREADS; int row = idx >> 3, sg = idx & 7;
            uint32_t off = row * 128 + sg * 16;
            asm volatile("cp.async.cg.shared.global [%0], [%1], 16;"
                :: "r"(sb + OFF_AL + SW128(off)), "l"(srcA + row * 256 + 128 + sg * 16));
        }
        #pragma unroll
        for (int it = 0; it < 4; it++) {   // Bh: 512 x 16B
            int idx = tid + it * NTHREADS; int row = idx >> 3, sg = idx & 7;
            uint32_t off = row * 128 + sg * 16;
            asm volatile("cp.async.cg.shared.global [%0], [%1], 16;"
                :: "r"(sb + OFF_BH + SW128(off)), "l"(srcB + row * 256 + sg * 16));
        }
        #pragma unroll
        for (int it = 0; it < 4; it++) {   // Bl
            int idx = tid + it * NTHREADS; int row = idx >> 3, sg = idx & 7;
            uint32_t off = row * 128 + sg * 16;
            asm volatile("cp.async.cg.shared.global [%0], [%1], 16;"
                :: "r"(sb + OFF_BL + SW128(off)), "l"(srcB + row * 256 + 128 + sg * 16));
        }
        asm volatile("cp.async.commit_group;" ::: "memory");
        asm volatile("cp.async.wait_group 0;" ::: "memory");
    }
    __syncthreads();

    // s32 accumulators: hh (weight 1) and cross (weight 1/128)
    int acc_h[4][4][4], acc_c[4][4][4];
    #pragma unroll
    for (int mi = 0; mi < 4; mi++)
        #pragma unroll
        for (int ni = 0; ni < 4; ni++)
            #pragma unroll
            for (int r = 0; r < 4; r++) { acc_h[mi][ni][r] = 0; acc_c[mi][ni][r] = 0; }

    // per-lane ldmatrix addressing (same byte layout as bf16 m16n8k16 — s8 m16n8k32
    // fragments are byte-identical). SW128 swizzle XOR = (row&7)*16.
    const uint32_t xorv = (L & 7) * 16;
    const uint32_t kha = (L >> 4) * 16;
    const uint32_t khb = ((L >> 3) & 1) * 16;
    uint32_t aBase[4], bBase[2];
    #pragma unroll
    for (int mi = 0; mi < 4; mi++)
        aBase[mi] = (uint32_t)(mb + mi * 16 + (L & 7) + ((L >> 3) & 1) * 8) * 128;
    #pragma unroll
    for (int p = 0; p < 2; p++)
        bBase[p] = (uint32_t)(nb + p * 16 + (L & 7) + ((L >> 4) & 1) * 8) * 128;

    // one pass = 4 k32-steps over a 128-byte K segment
    auto run_pass = [&](uint32_t aOff, uint32_t bOff, int (*acc)[4][4]) {
        #pragma unroll
        for (int ks = 0; ks < 4; ks++) {
            uint32_t a[4][4], b[4][2];
            #pragma unroll
            for (int mi = 0; mi < 4; mi++) {
                uint32_t addr = sb + aOff + aBase[mi] + (((uint32_t)ks * 32 + kha) ^ xorv);
                asm volatile("ldmatrix.sync.aligned.m8n8.x4.shared.b16 {%0,%1,%2,%3}, [%4];"
                    : "=r"(a[mi][0]), "=r"(a[mi][1]), "=r"(a[mi][2]), "=r"(a[mi][3]) : "r"(addr));
            }
            #pragma unroll
            for (int p = 0; p < 2; p++) {
                uint32_t addr = sb + bOff + bBase[p] + (((uint32_t)ks * 32 + khb) ^ xorv);
                asm volatile("ldmatrix.sync.aligned.m8n8.x4.shared.b16 {%0,%1,%2,%3}, [%4];"
                    : "=r"(b[2*p][0]), "=r"(b[2*p][1]), "=r"(b[2*p+1][0]), "=r"(b[2*p+1][1])
                    : "r"(addr));
            }
            #pragma unroll
            for (int mi = 0; mi < 4; mi++)
                #pragma unroll
                for (int ni = 0; ni < 4; ni++) {
                    asm volatile(
                        "mma.sync.aligned.m16n8k32.row.col.s32.s8.s8.s32 "
                        "{%0,%1,%2,%3}, {%4,%5,%6,%7}, {%8,%9}, {%0,%1,%2,%3};"
                        : "+r"(acc[mi][ni][0]), "+r"(acc[mi][ni][1]),
                          "+r"(acc[mi][ni][2]), "+r"(acc[mi][ni][3])
                        : "r"(a[mi][0]), "r"(a[mi][1]), "r"(a[mi][2]), "r"(a[mi][3]),
                          "r"(b[ni][0]), "r"(b[ni][1]));
                }
        }
    };

    run_pass(OFF_AH, OFF_BH, acc_h);   // hh
    run_pass(OFF_AH, OFF_BL, acc_c);   // h*l
    run_pass(OFF_AL, OFF_BH, acc_c);   // l*h

    // ---- epilogue: dot = sA*sB*(hh + cross/128) + a129*b129 (exact fp32) ----
    const float THMIN = 1.00000011920928955f;  // fp32(1 + 1e-7), identical to jnp
    const float LN2 = 0.69314718055994531f;
    float sbv[8], b129v[8];
    #pragma unroll
    for (int ni = 0; ni < 4; ni++) {
        int c = nb + ni * 8 + (L & 3) * 2;
        sbv[ni*2]     = g_sB[n0 + c];
        sbv[ni*2+1]   = g_sB[n0 + c + 1];
        b129v[ni*2]   = g_B129[n0 + c];
        b129v[ni*2+1] = g_B129[n0 + c + 1];
    }
    #pragma unroll
    for (int mi = 0; mi < 4; mi++) {
        const int rr = mb + mi * 16 + (L >> 2);
        const float sa0 = g_sA[m0 + rr],      sa8 = g_sA[m0 + rr + 8];
        const float a0  = g_A129[m0 + rr],    a8  = g_A129[m0 + rr + 8];
        const int r0 = m0 + rr;
        #pragma unroll
        for (int ni = 0; ni < 4; ni++) {
            const int col = n0 + nb + ni * 8 + (L & 3) * 2;
            const float sam[4] = {sa0, sa0, sa8, sa8};
            const float aam[4] = {a0, a0, a8, a8};
            float v[4];
            #pragma unroll
            for (int r = 0; r < 4; r++) {
                float t = fmaf(__int2float_rn(acc_c[mi][ni][r]), 0.0078125f,
                               __int2float_rn(acc_h[mi][ni][r]));
                float d = t * (sam[r] * sbv[ni*2 + (r & 1)]);
                float th = fmaxf(fmaf(-aam[r], b129v[ni*2 + (r & 1)], -d), THMIN);
                float x = fmaf(th, th, -1.0f);
                float sq; asm("sqrt.approx.f32 %0, %1;" : "=f"(sq) : "f"(x));
                float lg; asm("lg2.approx.f32 %0, %1;" : "=f"(lg) : "f"(th + sq));
                float s2 = lg * LN2;
                v[r] = -fminf(s2 * s2, 50.0f);
            }
            *(float2*)(out + (size_t)r0 * NUM_ITEMS + col)       = make_float2(v[0], v[1]);
            *(float2*)(out + (size_t)(r0 + 8) * NUM_ITEMS + col) = make_float2(v[2], v[3]);
        }
    }
}

extern "C" void kernel_launch(void* const* d_in, const int* in_sizes, int n_in,
                              void* d_out, int out_size) {
    const float* h = (const float*)d_in[0];
    float* out = (float*)d_out;

    const int totWarps = NUM_USERS + NUM_ITEMS;                 // one warp per row
    prep_kernel<<<(totWarps * 32 + 255) / 256, 256>>>(h);

    dim3 grid(NUM_USERS / BM, NUM_ITEMS / BN);                  // (64, 512)
    gemm_i8_kernel<<<grid, NTHREADS>>>(out);
}

// round 14
// speedup vs baseline: 2.7186x; 2.7186x over previous
#include <cuda_runtime.h>
#include <cuda_fp16.h>
#include <cstdint>
#include <math.h>

#define NUM_USERS 8192
#define NUM_ITEMS 32768
#define FEAT      129
#define BM        128
#define BN        128
#define NTHREADS  128              // 4 warps, each 64x64

// ---- scratch (__device__ globals: allocation-free) ----
// A (users): per row 256 halfs = [xh 0..127 | xl 128..255], x ~= xh + xl (fp16 pair, ~22 bits)
// B (items): per row 128 halfs  = yh (fp16), sign fold on k=0
__device__ __align__(256) __half g_A16[(size_t)NUM_USERS * 256];
__device__ __align__(256) __half g_B16[(size_t)NUM_ITEMS * 128];
__device__ float g_A129[NUM_USERS];   // feature 128, exact fp32 (rank-1 peel)
__device__ float g_B129[NUM_ITEMS];

__device__ __forceinline__ uint32_t smem_u32(const void* p) {
    uint32_t a;
    asm("{ .reg .u64 t; cvta.to.shared.u64 t, %1; cvt.u32.u64 %0, t; }" : "=r"(a) : "l"(p));
    return a;
}
#define SW128(off) ((off) ^ (((off) >> 3) & 0x70))

// ---- prep: sign fold, users -> (hi, lo) fp16, items -> fp16, rank-1 vectors ----
__global__ void prep_kernel(const float* __restrict__ h) {
    int idx = blockIdx.x * blockDim.x + threadIdx.x;
    const int totA = NUM_USERS * 128;
    const int totB = NUM_ITEMS * 128;
    if (idx < totA) {
        int u = idx >> 7, k = idx & 127;
        float x = h[(size_t)u * FEAT + k];
        __half xh = __float2half_rn(x);
        __half xl = __float2half_rn(x - __half2float(xh));
        g_A16[(size_t)u * 256 + k]       = xh;
        g_A16[(size_t)u * 256 + 128 + k] = xl;
    } else if (idx < totA + totB) {
        int j = idx - totA;
        int i = j >> 7, k = j & 127;
        float y = h[(size_t)(NUM_USERS + i) * FEAT + k];
        if (k == 0) y = -y;   // signs[0] = -1 folded into items
        g_B16[(size_t)i * 128 + k] = __float2half_rn(y);
    } else if (idx < totA + totB + NUM_USERS) {
        int u = idx - totA - totB;
        g_A129[u] = h[(size_t)u * FEAT + 128];
    } else if (idx < totA + totB + NUM_USERS + NUM_ITEMS) {
        int i = idx - totA - totB - NUM_USERS;
        g_B129[i] = h[(size_t)(NUM_USERS + i) * FEAT + 128];
    }
}

// smem blocks of 16KB (128 rows x 128B, SW128): [Ah0|Ah1|Al0|Al1|B0|B1] = 96KB
#define OFF_AH 0
#define OFF_AL 32768
#define OFF_B  65536
#define SM_SIZE 98304

__global__ __launch_bounds__(NTHREADS, 2)
void gemm_f16_kernel(float* __restrict__ out) {
    extern __shared__ __align__(1024) char smem[];
    const uint32_t sb = smem_u32(smem);
    const int tid = threadIdx.x;
    const int wid = tid >> 5;
    const int L = tid & 31;
    const int m0 = blockIdx.x * BM;
    const int n0 = blockIdx.y * BN;
    const int mb = (wid & 1) * 64;    // 2 warps in m
    const int nb = (wid >> 1) * 64;   // 2 warps in n

    // ---- one-shot cooperative load of full K via cp.async (96KB, no pipeline) ----
    {
        const __half* srcA = g_A16 + (size_t)m0 * 256;
        const __half* srcB = g_B16 + (size_t)n0 * 128;
        #pragma unroll
        for (int c = 0; c < 2; c++) {
            #pragma unroll
            for (int it = 0; it < 8; it++) {   // Ah chunk c: 1024 x 16B
                int idx = tid + it * NTHREADS; int row = idx >> 3, sg = idx & 7;
                uint32_t off = row * 128 + sg * 16;
                asm volatile("cp.async.cg.shared.global [%0], [%1], 16;"
                    :: "r"(sb + OFF_AH + c * 16384 + SW128(off)),
                       "l"(srcA + row * 256 + c * 64 + sg * 8));
            }
            #pragma unroll
            for (int it = 0; it < 8; it++) {   // Al chunk c
                int idx = tid + it * NTHREADS; int row = idx >> 3, sg = idx & 7;
                uint32_t off = row * 128 + sg * 16;
                asm volatile("cp.async.cg.shared.global [%0], [%1], 16;"
                    :: "r"(sb + OFF_AL + c * 16384 + SW128(off)),
                       "l"(srcA + row * 256 + 128 + c * 64 + sg * 8));
            }
            #pragma unroll
            for (int it = 0; it < 8; it++) {   // B chunk c
                int idx = tid + it * NTHREADS; int row = idx >> 3, sg = idx & 7;
                uint32_t off = row * 128 + sg * 16;
                asm volatile("cp.async.cg.shared.global [%0], [%1], 16;"
                    :: "r"(sb + OFF_B + c * 16384 + SW128(off)),
                       "l"(srcB + row * 128 + c * 64 + sg * 8));
            }
        }
        asm volatile("cp.async.commit_group;" ::: "memory");
        asm volatile("cp.async.wait_group 0;" ::: "memory");
    }
    __syncthreads();

    float acc[4][8][4];               // 128 fp32 accum per lane (64x64 warp tile)
    #pragma unroll
    for (int mi = 0; mi < 4; mi++)
        #pragma unroll
        for (int ni = 0; ni < 8; ni++)
            #pragma unroll
            for (int r = 0; r < 4; r++) acc[mi][ni][r] = 0.0f;

    // per-lane ldmatrix addressing (SW128 swizzle: XOR = (row&7)*16)
    const uint32_t xorv = (L & 7) * 16;
    const uint32_t kha = (L >> 4) * 16;
    const uint32_t khb = ((L >> 3) & 1) * 16;
    uint32_t aBase[4], bBase[4];
    #pragma unroll
    for (int mi = 0; mi < 4; mi++)
        aBase[mi] = (uint32_t)(mb + mi * 16 + (L & 7) + ((L >> 3) & 1) * 8) * 128;
    #pragma unroll
    for (int p = 0; p < 4; p++)
        bBase[p] = (uint32_t)(nb + p * 16 + (L & 7) + ((L >> 4) & 1) * 8) * 128;

    // mainloop: 2 chunks x 4 k16-steps; B fragment loaded once, used by Ah and Al MMAs
    #pragma unroll
    for (int c = 0; c < 2; c++) {
        #pragma unroll
        for (int ks = 0; ks < 4; ks++) {
            const uint32_t kofs = ((uint32_t)ks * 32);
            uint32_t b[8][2];
            #pragma unroll
            for (int p = 0; p < 4; p++) {
                uint32_t addr = sb + OFF_B + c * 16384 + bBase[p] + ((kofs + khb) ^ xorv);
                asm volatile("ldmatrix.sync.aligned.m8n8.x4.shared.b16 {%0,%1,%2,%3}, [%4];"
                    : "=r"(b[2*p][0]), "=r"(b[2*p][1]), "=r"(b[2*p+1][0]), "=r"(b[2*p+1][1])
                    : "r"(addr));
            }
            uint32_t ah[4][4], al[4][4];
            #pragma unroll
            for (int mi = 0; mi < 4; mi++) {
                uint32_t addr = sb + OFF_AH + c * 16384 + aBase[mi] + ((kofs + kha) ^ xorv);
                asm volatile("ldmatrix.sync.aligned.m8n8.x4.shared.b16 {%0,%1,%2,%3}, [%4];"
                    : "=r"(ah[mi][0]), "=r"(ah[mi][1]), "=r"(ah[mi][2]), "=r"(ah[mi][3])
                    : "r"(addr));
            }
            #pragma unroll
            for (int mi = 0; mi < 4; mi++)
                #pragma unroll
                for (int ni = 0; ni < 8; ni++) {
                    const uint32_t* bb = &b[ni][0];
                    asm volatile(
                        "mma.sync.aligned.m16n8k16.row.col.f32.f16.f16.f32 "
                        "{%0,%1,%2,%3}, {%4,%5,%6,%7}, {%8,%9}, {%0,%1,%2,%3};"
                        : "+f"(acc[mi][ni][0]), "+f"(acc[mi][ni][1]),
                          "+f"(acc[mi][ni][2]), "+f"(acc[mi][ni][3])
                        : "r"(ah[mi][0]), "r"(ah[mi][1]), "r"(ah[mi][2]), "r"(ah[mi][3]),
                          "r"(bb[0]), "r"(bb[1]));
                }
            #pragma unroll
            for (int mi = 0; mi < 4; mi++) {
                uint32_t addr = sb + OFF_AL + c * 16384 + aBase[mi] + ((kofs + kha) ^ xorv);
                asm volatile("ldmatrix.sync.aligned.m8n8.x4.shared.b16 {%0,%1,%2,%3}, [%4];"
                    : "=r"(al[mi][0]), "=r"(al[mi][1]), "=r"(al[mi][2]), "=r"(al[mi][3])
                    : "r"(addr));
            }
            #pragma unroll
            for (int mi = 0; mi < 4; mi++)
                #pragma unroll
                for (int ni = 0; ni < 8; ni++) {
                    const uint32_t* bb = &b[ni][0];
                    asm volatile(
                        "mma.sync.aligned.m16n8k16.row.col.f32.f16.f16.f32 "
                        "{%0,%1,%2,%3}, {%4,%5,%6,%7}, {%8,%9}, {%0,%1,%2,%3};"
                        : "+f"(acc[mi][ni][0]), "+f"(acc[mi][ni][1]),
                          "+f"(acc[mi][ni][2]), "+f"(acc[mi][ni][3])
                        : "r"(al[mi][0]), "r"(al[mi][1]), "r"(al[mi][2]), "r"(al[mi][3]),
                          "r"(bb[0]), "r"(bb[1]));
                }
        }
    }

    // ---- fused epilogue: dot = acc + a129*b129 (exact fp32 rank-1 peel) ----
    const float THMIN = 1.00000011920928955f;  // fp32(1 + 1e-7), identical to jnp
    const float LN2 = 0.69314718055994531f;
    float b129v[16];
    #pragma unroll
    for (int ni = 0; ni < 8; ni++) {
        int cc = nb + ni * 8 + (L & 3) * 2;
        b129v[ni*2]   = g_B129[n0 + cc];
        b129v[ni*2+1] = g_B129[n0 + cc + 1];
    }
    #pragma unroll
    for (int mi = 0; mi < 4; mi++) {
        const int rr = mb + mi * 16 + (L >> 2);
        const float a0 = g_A129[m0 + rr], a8 = g_A129[m0 + rr + 8];
        const int r0 = m0 + rr;
        #pragma unroll
        for (int ni = 0; ni < 8; ni++) {
            const int col = n0 + nb + ni * 8 + (L & 3) * 2;
            const float aam[4] = {a0, a0, a8, a8};
            float v[4];
            #pragma unroll
            for (int r = 0; r < 4; r++) {
                float th = fmaxf(fmaf(-aam[r], b129v[ni*2 + (r & 1)], -acc[mi][ni][r]), THMIN);
                float x = fmaf(th, th, -1.0f);
                float sq; asm("sqrt.approx.f32 %0, %1;" : "=f"(sq) : "f"(x));
                float lg; asm("lg2.approx.f32 %0, %1;" : "=f"(lg) : "f"(th + sq));
                float s2 = lg * LN2;
                v[r] = -fminf(s2 * s2, 50.0f);
            }
            *(float2*)(out + (size_t)r0 * NUM_ITEMS + col)       = make_float2(v[0], v[1]);
            *(float2*)(out + (size_t)(r0 + 8) * NUM_ITEMS + col) = make_float2(v[2], v[3]);
        }
    }
}

extern "C" void kernel_launch(void* const* d_in, const int* in_sizes, int n_in,
                              void* d_out, int out_size) {
    const float* h = (const float*)d_in[0];
    float* out = (float*)d_out;

    const int totPrep = (NUM_USERS + NUM_ITEMS) * 128 + NUM_USERS + NUM_ITEMS;
    prep_kernel<<<(totPrep + 255) / 256, 256>>>(h);

    cudaFuncSetAttribute(gemm_f16_kernel, cudaFuncAttributeMaxDynamicSharedMemorySize, SM_SIZE);
    dim3 grid(NUM_USERS / BM, NUM_ITEMS / BN);  // (64, 256)
    gemm_f16_kernel<<<grid, NTHREADS, SM_SIZE>>>(out);
}

// round 15
// speedup vs baseline: 2.9769x; 1.0950x over previous
#include <cuda_runtime.h>
#include <cuda_fp16.h>
#include <cstdint>
#include <math.h>

#define NUM_USERS 8192
#define NUM_ITEMS 32768
#define FEAT      129
#define BM        128
#define BN        128
#define NTHREADS  128              // 4 warps, each 64x64

// ---- scratch (__device__ globals: allocation-free) ----
// A (users): per row 256 halfs = [xh 0..127 | xl 128..255], x ~= xh + xl (fp16 pair)
// B (items): per row 128 halfs = yh (fp16), sign fold on k=0
__device__ __align__(256) __half g_A16[(size_t)NUM_USERS * 256];
__device__ __align__(256) __half g_B16[(size_t)NUM_ITEMS * 128];
__device__ float g_A129[NUM_USERS];   // feature 128, exact fp32 (rank-1 peel)
__device__ float g_B129[NUM_ITEMS];

__device__ __forceinline__ uint32_t smem_u32(const void* p) {
    uint32_t a;
    asm("{ .reg .u64 t; cvta.to.shared.u64 t, %1; cvt.u32.u64 %0, t; }" : "=r"(a) : "l"(p));
    return a;
}
#define SW128(off) ((off) ^ (((off) >> 3) & 0x70))

// ---- prep: sign fold, users -> (hi, lo) fp16, items -> fp16, rank-1 vectors ----
__global__ void prep_kernel(const float* __restrict__ h) {
    int idx = blockIdx.x * blockDim.x + threadIdx.x;
    const int totA = NUM_USERS * 128;
    const int totB = NUM_ITEMS * 128;
    if (idx < totA) {
        int u = idx >> 7, k = idx & 127;
        float x = h[(size_t)u * FEAT + k];
        __half xh = __float2half_rn(x);
        __half xl = __float2half_rn(x - __half2float(xh));
        g_A16[(size_t)u * 256 + k]       = xh;
        g_A16[(size_t)u * 256 + 128 + k] = xl;
    } else if (idx < totA + totB) {
        int j = idx - totA;
        int i = j >> 7, k = j & 127;
        float y = h[(size_t)(NUM_USERS + i) * FEAT + k];
        if (k == 0) y = -y;   // signs[0] = -1 folded into items
        g_B16[(size_t)i * 128 + k] = __float2half_rn(y);
    } else if (idx < totA + totB + NUM_USERS) {
        int u = idx - totA - totB;
        g_A129[u] = h[(size_t)u * FEAT + 128];
    } else if (idx < totA + totB + NUM_USERS + NUM_ITEMS) {
        int i = idx - totA - totB - NUM_USERS;
        g_B129[i] = h[(size_t)(NUM_USERS + i) * FEAT + 128];
    }
}

// smem 16KB blocks (128 rows x 128B, SW128): [Ah0|Ah1|Al0|Al1|B0|B1] = 96KB
#define OFF_AH 0
#define OFF_AL 32768
#define OFF_B  65536
#define SM_SIZE 98304

__global__ __launch_bounds__(NTHREADS, 2)
void gemm_f16_kernel(float* __restrict__ out) {
    extern __shared__ __align__(1024) char smem[];
    const uint32_t sb = smem_u32(smem);
    const int tid = threadIdx.x;
    const int wid = tid >> 5;
    const int L = tid & 31;
    const int m0 = blockIdx.x * BM;
    const int n0 = blockIdx.y * BN;
    const int mb = (wid & 1) * 64;    // 2 warps in m
    const int nb = (wid >> 1) * 64;   // 2 warps in n

    // ---- cooperative load, 2 commit groups (chunk0 then chunk1) ----
    {
        const __half* srcA = g_A16 + (size_t)m0 * 256;
        const __half* srcB = g_B16 + (size_t)n0 * 128;
        #pragma unroll
        for (int c = 0; c < 2; c++) {
            #pragma unroll
            for (int it = 0; it < 8; it++) {   // Ah chunk c: 1024 x 16B
                int idx = tid + it * NTHREADS; int row = idx >> 3, sg = idx & 7;
                uint32_t off = row * 128 + sg * 16;
                asm volatile("cp.async.cg.shared.global [%0], [%1], 16;"
                    :: "r"(sb + OFF_AH + c * 16384 + SW128(off)),
                       "l"(srcA + row * 256 + c * 64 + sg * 8));
            }
            #pragma unroll
            for (int it = 0; it < 8; it++) {   // Al chunk c
                int idx = tid + it * NTHREADS; int row = idx >> 3, sg = idx & 7;
                uint32_t off = row * 128 + sg * 16;
                asm volatile("cp.async.cg.shared.global [%0], [%1], 16;"
                    :: "r"(sb + OFF_AL + c * 16384 + SW128(off)),
                       "l"(srcA + row * 256 + 128 + c * 64 + sg * 8));
            }
            #pragma unroll
            for (int it = 0; it < 8; it++) {   // B chunk c
                int idx = tid + it * NTHREADS; int row = idx >> 3, sg = idx & 7;
                uint32_t off = row * 128 + sg * 16;
                asm volatile("cp.async.cg.shared.global [%0], [%1], 16;"
                    :: "r"(sb + OFF_B + c * 16384 + SW128(off)),
                       "l"(srcB + row * 128 + c * 64 + sg * 8));
            }
            asm volatile("cp.async.commit_group;" ::: "memory");
        }
    }

    // acc[half][mi2][ni][r]: two 64-reg banks (M-halves of the 64x64 warp tile)
    float acc[2][2][8][4];
    #pragma unroll
    for (int hh = 0; hh < 2; hh++)
        #pragma unroll
        for (int mi = 0; mi < 2; mi++)
            #pragma unroll
            for (int ni = 0; ni < 8; ni++)
                #pragma unroll
                for (int r = 0; r < 4; r++) acc[hh][mi][ni][r] = 0.0f;

    // per-lane ldmatrix addressing (SW128 swizzle: XOR = (row&7)*16)
    const uint32_t xorv = (L & 7) * 16;
    const uint32_t kha = (L >> 4) * 16;
    const uint32_t khb = ((L >> 3) & 1) * 16;
    uint32_t aBase[4], bBase[4];
    #pragma unroll
    for (int mi = 0; mi < 4; mi++)
        aBase[mi] = (uint32_t)(mb + mi * 16 + (L & 7) + ((L >> 3) & 1) * 8) * 128;
    #pragma unroll
    for (int p = 0; p < 4; p++)
        bBase[p] = (uint32_t)(nb + p * 16 + (L & 7) + ((L >> 4) & 1) * 8) * 128;

    // preload rank-1 scalars (overlaps cp.async flight)
    float a129v[8], b129v[16];
    #pragma unroll
    for (int mi = 0; mi < 4; mi++) {
        int rr = mb + mi * 16 + (L >> 2);
        a129v[mi * 2]     = g_A129[m0 + rr];
        a129v[mi * 2 + 1] = g_A129[m0 + rr + 8];
    }
    #pragma unroll
    for (int ni = 0; ni < 8; ni++) {
        int cc = nb + ni * 8 + (L & 3) * 2;
        b129v[ni * 2]     = g_B129[n0 + cc];
        b129v[ni * 2 + 1] = g_B129[n0 + cc + 1];
    }

    // one k16-step of MMAs for M-half h on chunk c: 8 ldsm + 32 HMMA
    auto mma_step = [&](int h, int c, int ks) {
        const uint32_t kofs = (uint32_t)ks * 32;
        uint32_t b[8][2];
        #pragma unroll
        for (int p = 0; p < 4; p++) {
            uint32_t addr = sb + OFF_B + c * 16384 + bBase[p] + ((kofs + khb) ^ xorv);
            asm volatile("ldmatrix.sync.aligned.m8n8.x4.shared.b16 {%0,%1,%2,%3}, [%4];"
                : "=r"(b[2*p][0]), "=r"(b[2*p][1]), "=r"(b[2*p+1][0]), "=r"(b[2*p+1][1])
                : "r"(addr));
        }
        uint32_t ah[2][4], al[2][4];
        #pragma unroll
        for (int mi = 0; mi < 2; mi++) {
            uint32_t addr = sb + OFF_AH + c * 16384 + aBase[h*2+mi] + ((kofs + kha) ^ xorv);
            asm volatile("ldmatrix.sync.aligned.m8n8.x4.shared.b16 {%0,%1,%2,%3}, [%4];"
                : "=r"(ah[mi][0]), "=r"(ah[mi][1]), "=r"(ah[mi][2]), "=r"(ah[mi][3]) : "r"(addr));
        }
        #pragma unroll
        for (int mi = 0; mi < 2; mi++) {
            uint32_t addr = sb + OFF_AL + c * 16384 + aBase[h*2+mi] + ((kofs + kha) ^ xorv);
            asm volatile("ldmatrix.sync.aligned.m8n8.x4.shared.b16 {%0,%1,%2,%3}, [%4];"
                : "=r"(al[mi][0]), "=r"(al[mi][1]), "=r"(al[mi][2]), "=r"(al[mi][3]) : "r"(addr));
        }
        #pragma unroll
        for (int mi = 0; mi < 2; mi++)
            #pragma unroll
            for (int ni = 0; ni < 8; ni++) {
                asm volatile(
                    "mma.sync.aligned.m16n8k16.row.col.f32.f16.f16.f32 "
                    "{%0,%1,%2,%3}, {%4,%5,%6,%7}, {%8,%9}, {%0,%1,%2,%3};"
                    : "+f"(acc[h][mi][ni][0]), "+f"(acc[h][mi][ni][1]),
                      "+f"(acc[h][mi][ni][2]), "+f"(acc[h][mi][ni][3])
                    : "r"(ah[mi][0]), "r"(ah[mi][1]), "r"(ah[mi][2]), "r"(ah[mi][3]),
                      "r"(b[ni][0]), "r"(b[ni][1]));
            }
        #pragma unroll
        for (int mi = 0; mi < 2; mi++)
            #pragma unroll
            for (int ni = 0; ni < 8; ni++) {
                asm volatile(
                    "mma.sync.aligned.m16n8k16.row.col.f32.f16.f16.f32 "
                    "{%0,%1,%2,%3}, {%4,%5,%6,%7}, {%8,%9}, {%0,%1,%2,%3};"
                    : "+f"(acc[h][mi][ni][0]), "+f"(acc[h][mi][ni][1]),
                      "+f"(acc[h][mi][ni][2]), "+f"(acc[h][mi][ni][3])
                    : "r"(al[mi][0]), "r"(al[mi][1]), "r"(al[mi][2]), "r"(al[mi][3]),
                      "r"(b[ni][0]), "r"(b[ni][1]));
            }
    };

    // epilogue for one (half, group): group g -> mi2 = g>>3, ni = g&7 (4 outputs)
    const float THMIN = 1.00000011920928955f;   // fp32(1 + 1e-7), identical to jnp
    const float NEGLN2SQ = -0.480453013918201f; // -(ln2)^2
    const float CLIP = -50.0f;
    auto epi_group = [&](int h, int g) {
        const int mi2 = g >> 3, ni = g & 7;
        const int mi = h * 2 + mi2;
        const int r0 = m0 + mb + mi * 16 + (L >> 2);
        const int col = n0 + nb + ni * 8 + (L & 3) * 2;
        const float aam[4] = {a129v[mi*2], a129v[mi*2], a129v[mi*2+1], a129v[mi*2+1]};
        float v[4];
        #pragma unroll
        for (int r = 0; r < 4; r++) {
            float th = fmaxf(fmaf(-aam[r], b129v[ni*2 + (r & 1)], -acc[h][mi2][ni][r]), THMIN);
            float x = fmaf(th, th, -1.0f);
            float sq; asm("sqrt.approx.f32 %0, %1;" : "=f"(sq) : "f"(x));
            float lg; asm("lg2.approx.f32 %0, %1;" : "=f"(lg) : "f"(th + sq));
            v[r] = fmaxf(lg * lg * NEGLN2SQ, CLIP);
        }
        *(float2*)(out + (size_t)r0 * NUM_ITEMS + col)       = make_float2(v[0], v[1]);
        *(float2*)(out + (size_t)(r0 + 8) * NUM_ITEMS + col) = make_float2(v[2], v[3]);
    };

    // ---- Phase A: half0 MMA (chunk0 while chunk1 lands) ----
    asm volatile("cp.async.wait_group 1;" ::: "memory");
    __syncthreads();
    #pragma unroll
    for (int ks = 0; ks < 4; ks++) mma_step(0, 0, ks);
    asm volatile("cp.async.wait_group 0;" ::: "memory");
    __syncthreads();
    #pragma unroll
    for (int ks = 0; ks < 4; ks++) mma_step(0, 1, ks);

    // ---- Phase B: half1 MMA interleaved with half0 epilogue ----
    #pragma unroll
    for (int s = 0; s < 8; s++) {
        mma_step(1, s >> 2, s & 3);
        epi_group(0, 2 * s);
        epi_group(0, 2 * s + 1);
    }

    // ---- Phase C: half1 epilogue ----
    #pragma unroll
    for (int g = 0; g < 16; g++) epi_group(1, g);
}

extern "C" void kernel_launch(void* const* d_in, const int* in_sizes, int n_in,
                              void* d_out, int out_size) {
    const float* h = (const float*)d_in[0];
    float* out = (float*)d_out;

    const int totPrep = (NUM_USERS + NUM_ITEMS) * 128 + NUM_USERS + NUM_ITEMS;
    prep_kernel<<<(totPrep + 255) / 256, 256>>>(h);

    cudaFuncSetAttribute(gemm_f16_kernel, cudaFuncAttributeMaxDynamicSharedMemorySize, SM_SIZE);
    dim3 grid(NUM_USERS / BM, NUM_ITEMS / BN);  // (64, 256)
    gemm_f16_kernel<<<grid, NTHREADS, SM_SIZE>>>(out);
}